// round 8
// baseline (speedup 1.0000x reference)
#include <cuda_runtime.h>
#include <cuda_bf16.h>
#include <stdint.h>

// SimpleMovingAverage: history (64, 336, 862, 3) f32.
// window = last Q=12 steps; 336 iterations of m = mean(window), push m.
//
// R4-R6 invariant: the write phase pins at ~46.7us regardless of occupancy /
// chunking / cache hints -> scalar STG.64 issue + misaligned 3-line warp
// stores are the binder (L1tex 54-58% every round). This round removes STG
// from the hot loop: means are staged in a double-buffered SMEM tile
// [12 rows x 1024B] and drained with cp.async.bulk (UBLKCP, bulk/TMA path,
// no L1 wavefronts). Output rows are 10344B (== 8 mod 16), so odd-parity rows
// are staged at +8B in SMEM making both bulk src and dst 16B-aligned; the
// 2-float head/tail of odd rows are patched by scalar STG (24 per tile).
//
// Time split: 7 chunks x 48 steps (48 = 4*12 keeps the register ring
// statically indexed). Chunk c derives its start window from the 12 input
// values via compile-time matrices A^(48c) in __constant__ memory.
// Per-step critical path: 1 FFMA:  m = s/12;  s = fma(s, 13/12, -w[u]).

#define SMA_Q       12
#define SMA_INLEN   336
#define SMA_OUTLEN  336
#define SMA_ROW     2586          // 862*3 floats, contiguous (10344 B)
#define SMA_ROW2    (SMA_ROW / 2) // 1293 float2 per row
#define SMA_BATCH   64

#define SMA_CHUNKS  7
#define SMA_CSTEPS  (SMA_OUTLEN / SMA_CHUNKS)  // 48 = 4 * 12

#define SMA_W2      128           // float2 series per block (256 floats)
#define TILE_ROWS   12
#define TILE_PITCH  1040          // 1024 data + 16 pad; multiple of 16

struct SmaMats {
    float m[SMA_CHUNKS - 1][SMA_Q][SMA_Q];
};

static constexpr SmaMats sma_compute_mats() {
    SmaMats r = {};
    for (int k = 0; k < SMA_Q; k++) {
        float w[SMA_Q] = {};
        for (int i = 0; i < SMA_Q; i++) w[i] = (i == k) ? 1.0f : 0.0f;
        float s = 1.0f;
        for (int c = 0; c < SMA_CHUNKS - 1; c++) {
            for (int t = 0; t < SMA_CSTEPS; t++) {
                int u = t % SMA_Q;
                float mean = s * (1.0f / 12.0f);
                s = s * (13.0f / 12.0f) - w[u];
                w[u] = mean;
            }
            for (int j = 0; j < SMA_Q; j++) r.m[c][k][j] = w[j];
        }
    }
    return r;
}

__constant__ SmaMats c_MATS = sma_compute_mats();

__device__ __forceinline__ uint32_t smem_u32(const void* p) {
    return (uint32_t)__cvta_generic_to_shared(p);
}

template <int CHUNK>
__device__ __forceinline__ void sma_block(const float* __restrict__ in,
                                          float* __restrict__ out)
{
    __shared__ __align__(16) char tiles[2][TILE_ROWS * TILE_PITCH];

    const int tid   = threadIdx.x;
    const int colf2 = blockIdx.x * SMA_W2;        // float2 column offset
    const int b     = blockIdx.y;

    int nser = SMA_ROW2 - colf2;
    if (nser > SMA_W2) nser = SMA_W2;
    const bool active = (tid < nser);
    const int  Wbytes = nser * 8;                 // bytes of row data staged

    // ---- starting window for this chunk ----
    float wx[SMA_Q], wy[SMA_Q];
    float sx = 0.0f, sy = 0.0f;

    const float2* __restrict__ src =
        reinterpret_cast<const float2*>(
            in + (size_t)b * SMA_INLEN * SMA_ROW
               + (size_t)(SMA_INLEN - SMA_Q) * SMA_ROW) + (colf2 + tid);

    if (active) {
        if (CHUNK == 0) {
#pragma unroll
            for (int k = 0; k < SMA_Q; k++) {
                float2 v = src[(size_t)k * SMA_ROW2];
                wx[k] = v.x; wy[k] = v.y;
                sx += v.x;   sy += v.y;
            }
        } else {
#pragma unroll
            for (int j = 0; j < SMA_Q; j++) { wx[j] = 0.0f; wy[j] = 0.0f; }
#pragma unroll
            for (int k = 0; k < SMA_Q; k++) {
                float2 v = src[(size_t)k * SMA_ROW2];
#pragma unroll
                for (int j = 0; j < SMA_Q; j++) {
                    float c = c_MATS.m[CHUNK - 1][k][j];
                    wx[j] = fmaf(c, v.x, wx[j]);
                    wy[j] = fmaf(c, v.y, wy[j]);
                }
            }
#pragma unroll
            for (int j = 0; j < SMA_Q; j++) { sx += wx[j]; sy += wy[j]; }
        }
    } else {
#pragma unroll
        for (int j = 0; j < SMA_Q; j++) { wx[j] = 0.0f; wy[j] = 0.0f; }
    }

    const float inv_q = 1.0f / 12.0f;
    const float k1312 = 13.0f / 12.0f;

    // output row index base for this (b, chunk); parity of (base + blk*12 + u)
    // is (u & 1) because base and blk*12 are even.
    const size_t rowbase = (size_t)b * SMA_OUTLEN + (size_t)CHUNK * SMA_CSTEPS;

#pragma unroll 1
    for (int blk = 0; blk < SMA_CSTEPS / TILE_ROWS; blk++) {
        char* tile = tiles[blk & 1];

        // ---- fill tile: 12 recurrence steps, means -> SMEM ----
#pragma unroll
        for (int u = 0; u < TILE_ROWS; u++) {
            float mx = sx * inv_q;
            float my = sy * inv_q;
            if (active) {
                *reinterpret_cast<float2*>(
                    tile + u * TILE_PITCH + ((u & 1) * 8) + tid * 8)
                    = make_float2(mx, my);
            }
            sx = fmaf(sx, k1312, -wx[u]);
            sy = fmaf(sy, k1312, -wy[u]);
            wx[u] = mx;
            wy[u] = my;
        }

        asm volatile("fence.proxy.async.shared::cta;" ::: "memory");
        __syncthreads();

        // ---- drain tile ----
        if (tid < TILE_ROWS) {
            // bulk copy lane: one row each
            const int r = tid;
            const size_t row = rowbase + (size_t)blk * TILE_ROWS + r;
            char* g = reinterpret_cast<char*>(out + row * SMA_ROW + colf2 * 2);
            const int head = (r & 1) * 8;              // phase-8 rows
            const int bulk = (Wbytes - head) & ~15;
            // smem data base = r*PITCH + (r&1)*8; bulk src = +head more
            uint32_t s = smem_u32(tile + r * TILE_PITCH + (r & 1) * 16);
            if (bulk > 0) {
                asm volatile(
                    "cp.async.bulk.global.shared::cta.bulk_group [%0], [%1], %2;"
                    :: "l"(g + head), "r"(s), "r"((uint32_t)bulk) : "memory");
            }
            asm volatile("cp.async.bulk.commit_group;" ::: "memory");
            // previous flush of the OTHER buffer must have finished reading
            asm volatile("cp.async.bulk.wait_group.read 1;" ::: "memory");
        } else if (tid >= 32 && tid < 32 + TILE_ROWS) {
            // head patch lane (odd rows only): first 2 floats
            const int r = tid - 32;
            if ((r & 1) && Wbytes >= 8) {
                const size_t row = rowbase + (size_t)blk * TILE_ROWS + r;
                float2 v = *reinterpret_cast<const float2*>(
                    tile + r * TILE_PITCH + 8);
                *reinterpret_cast<float2*>(out + row * SMA_ROW + colf2 * 2) = v;
            }
        } else if (tid >= 64 && tid < 64 + TILE_ROWS) {
            // tail patch lane: last 2 floats when (Wbytes - head) % 16 != 0
            const int r = tid - 64;
            const int head = (r & 1) * 8;
            const int bulk = (Wbytes - head) & ~15;
            const int tailoff = head + bulk;
            if (tailoff < Wbytes) {
                const size_t row = rowbase + (size_t)blk * TILE_ROWS + r;
                float2 v = *reinterpret_cast<const float2*>(
                    tile + r * TILE_PITCH + (r & 1) * 8 + tailoff);
                *reinterpret_cast<float2*>(
                    reinterpret_cast<char*>(out + row * SMA_ROW + colf2 * 2)
                    + tailoff) = v;
            }
        }
        __syncthreads();
    }

    // ensure all bulk stores complete before exit
    if (tid < TILE_ROWS) {
        asm volatile("cp.async.bulk.wait_group 0;" ::: "memory");
    }
}

__global__ __launch_bounds__(128)
void sma_main_kernel(const float* __restrict__ in, float* __restrict__ out) {
    switch (blockIdx.z) {
        case 0: sma_block<0>(in, out); break;
        case 1: sma_block<1>(in, out); break;
        case 2: sma_block<2>(in, out); break;
        case 3: sma_block<3>(in, out); break;
        case 4: sma_block<4>(in, out); break;
        case 5: sma_block<5>(in, out); break;
        case 6: sma_block<6>(in, out); break;
        default: break;
    }
}

extern "C" void kernel_launch(void* const* d_in, const int* in_sizes, int n_in,
                              void* d_out, int out_size) {
    (void)in_sizes; (void)n_in; (void)out_size;
    const float* in = (const float*)d_in[0];
    float* out = (float*)d_out;

    // grid: (column blocks of 256 floats, batch, time chunk)
    const int colblocks = (SMA_ROW2 + SMA_W2 - 1) / SMA_W2;  // 11
    dim3 grid(colblocks, SMA_BATCH, SMA_CHUNKS);
    sma_main_kernel<<<grid, 128>>>(in, out);
}

// round 9
// speedup vs baseline: 1.7843x; 1.7843x over previous
#include <cuda_runtime.h>
#include <cuda_bf16.h>
#include <stdint.h>

// SimpleMovingAverage: history (64, 336, 862, 3) f32.
// window = last Q=12 steps; 336 iterations of m = mean(window), push m.
//
// Time split: 7 chunks x 48 steps (48 = 4*12 keeps register ring statically
// indexed); chunk start windows come from compile-time matrices A^(48c) in
// __constant__ memory (R6). New in R8: stores are staged through SMEM tiles
// [12 rows x ~1KB] and drained by ALL 128 threads as 16B-aligned STG.128
// (R7's bulk-copy drain starved on 12 lanes; this keeps every lane storing).
// Rows are staged at their GMEM 8-byte phase ((row&1)*8) so both LDS.128 and
// STG.128 are aligned; odd-row 8B head/tail handled by the slot-63 lane.
//
// Per-step critical path: 1 FFMA:  m = s/12;  s = fma(s, 13/12, -w[u]).

#define SMA_Q       12
#define SMA_INLEN   336
#define SMA_OUTLEN  336
#define SMA_ROW     2586          // 862*3 floats per row (10344 B)
#define SMA_ROW2    (SMA_ROW / 2) // 1293 float2 per row
#define SMA_BATCH   64

#define SMA_CHUNKS  7
#define SMA_CSTEPS  (SMA_OUTLEN / SMA_CHUNKS)  // 48 = 4 * 12

#define SMA_W2      128           // float2 series per full block (1024 B/row)
#define NFULL       (SMA_ROW2 / SMA_W2)        // 10 full col blocks
#define NPART       (SMA_ROW2 - NFULL * SMA_W2) // 13 leftover float2
#define TILE_ROWS   12
#define TILE_PITCH  1040          // 1024 data + 8 phase + pad, 16B multiple

struct SmaMats { float m[SMA_CHUNKS - 1][SMA_Q][SMA_Q]; };

static constexpr SmaMats sma_compute_mats() {
    SmaMats r = {};
    for (int k = 0; k < SMA_Q; k++) {
        float w[SMA_Q] = {};
        for (int i = 0; i < SMA_Q; i++) w[i] = (i == k) ? 1.0f : 0.0f;
        float s = 1.0f;
        for (int c = 0; c < SMA_CHUNKS - 1; c++) {
            for (int t = 0; t < SMA_CSTEPS; t++) {
                int u = t % SMA_Q;
                float mean = s * (1.0f / 12.0f);
                s = s * (13.0f / 12.0f) - w[u];
                w[u] = mean;
            }
            for (int j = 0; j < SMA_Q; j++) r.m[c][k][j] = w[j];
        }
    }
    return r;
}

__constant__ SmaMats c_MATS = sma_compute_mats();

// ---- shared init of the chunk-start window (lane-local) ----
template <int CHUNK>
__device__ __forceinline__ void sma_load_window(
    const float2* __restrict__ src, float wx[SMA_Q], float wy[SMA_Q],
    float& sx, float& sy)
{
    sx = 0.0f; sy = 0.0f;
    if (CHUNK == 0) {
#pragma unroll
        for (int k = 0; k < SMA_Q; k++) {
            float2 v = src[(size_t)k * SMA_ROW2];
            wx[k] = v.x; wy[k] = v.y;
            sx += v.x;   sy += v.y;
        }
    } else {
#pragma unroll
        for (int j = 0; j < SMA_Q; j++) { wx[j] = 0.0f; wy[j] = 0.0f; }
#pragma unroll
        for (int k = 0; k < SMA_Q; k++) {
            float2 v = src[(size_t)k * SMA_ROW2];
#pragma unroll
            for (int j = 0; j < SMA_Q; j++) {
                float c = c_MATS.m[CHUNK - 1][k][j];
                wx[j] = fmaf(c, v.x, wx[j]);
                wy[j] = fmaf(c, v.y, wy[j]);
            }
        }
#pragma unroll
        for (int j = 0; j < SMA_Q; j++) { sx += wx[j]; sy += wy[j]; }
    }
}

// ---- full column block: SMEM-staged aligned drain ----
template <int CHUNK>
__device__ __forceinline__ void sma_block_full(
    const float* __restrict__ in, float* __restrict__ out)
{
    __shared__ __align__(16) char tile[TILE_ROWS * TILE_PITCH];

    const int tid   = threadIdx.x;            // 0..127, all active
    const int colf2 = blockIdx.x * SMA_W2;
    const int b     = blockIdx.y;

    const float2* __restrict__ src =
        reinterpret_cast<const float2*>(
            in + (size_t)b * SMA_INLEN * SMA_ROW
               + (size_t)(SMA_INLEN - SMA_Q) * SMA_ROW) + (colf2 + tid);

    float wx[SMA_Q], wy[SMA_Q], sx, sy;
    sma_load_window<CHUNK>(src, wx, wy, sx, sy);

    const float inv_q = 1.0f / 12.0f;
    const float k1312 = 13.0f / 12.0f;

    // global output row base for this (b, chunk): even, so parity == u&1
    const size_t rowbase = (size_t)b * SMA_OUTLEN + (size_t)CHUNK * SMA_CSTEPS;
    // byte base of this block's column window within a row
    char* const outb = reinterpret_cast<char*>(out) + (size_t)colf2 * 8;

#pragma unroll 1
    for (int blk = 0; blk < SMA_CSTEPS / TILE_ROWS; blk++) {
        // ---- fill: 12 steps of the recurrence into SMEM (phase-staged) ----
#pragma unroll
        for (int u = 0; u < TILE_ROWS; u++) {
            float mx = sx * inv_q;
            float my = sy * inv_q;
            *reinterpret_cast<float2*>(
                tile + u * TILE_PITCH + ((u & 1) * 8) + tid * 8)
                = make_float2(mx, my);
            sx = fmaf(sx, k1312, -wx[u]);
            sy = fmaf(sy, k1312, -wy[u]);
            wx[u] = mx;
            wy[u] = my;
        }
        __syncthreads();

        // ---- drain: 12 rows x 64 slots, all threads, aligned STG.128 ----
        // even row r: slot k copies data bytes [16k,16k+16) ->
        //             dst = rowptr + 16k                        (aligned)
        // odd  row r: slot k<63 copies data bytes [8+16k, 24+16k) ->
        //             dst = rowptr + 8 + 16k                    (aligned)
        //             slot k==63 does the 8B head (d[0,8)) and tail
        //             (d[1016,1024)) as two STG.64.
        const size_t row0 = rowbase + (size_t)blk * TILE_ROWS;
#pragma unroll
        for (int it = 0; it < (TILE_ROWS * 64) / 128; it++) {
            int s   = it * 128 + tid;
            int r   = s >> 6;
            int k   = s & 63;
            char* rowp = outb + (row0 + r) * (size_t)(SMA_ROW * 4);
            char* sp   = tile + r * TILE_PITCH;
            if ((r & 1) == 0) {
                float4 v = *reinterpret_cast<const float4*>(sp + k * 16);
                *reinterpret_cast<float4*>(rowp + k * 16) = v;
            } else if (k < 63) {
                // staged at +8: data byte d lives at sp + 8 + d
                float4 v = *reinterpret_cast<const float4*>(sp + 16 + k * 16);
                *reinterpret_cast<float4*>(rowp + 8 + k * 16) = v;
            } else {
                float2 h = *reinterpret_cast<const float2*>(sp + 8);
                *reinterpret_cast<float2*>(rowp) = h;
                float2 t = *reinterpret_cast<const float2*>(sp + 8 + 1016);
                *reinterpret_cast<float2*>(rowp + 1016) = t;
            }
        }
        __syncthreads();   // tile reused next iteration
    }
}

// ---- partial last column block (13 float2): direct stores (R6 path) ----
template <int CHUNK>
__device__ __forceinline__ void sma_block_part(
    const float* __restrict__ in, float* __restrict__ out)
{
    const int tid = threadIdx.x;
    if (tid >= NPART) return;
    const int colf2 = NFULL * SMA_W2;
    const int b     = blockIdx.y;

    const float2* __restrict__ src =
        reinterpret_cast<const float2*>(
            in + (size_t)b * SMA_INLEN * SMA_ROW
               + (size_t)(SMA_INLEN - SMA_Q) * SMA_ROW) + (colf2 + tid);

    float wx[SMA_Q], wy[SMA_Q], sx, sy;
    sma_load_window<CHUNK>(src, wx, wy, sx, sy);

    float2* __restrict__ d =
        reinterpret_cast<float2*>(out + (size_t)b * SMA_OUTLEN * SMA_ROW
                                      + (size_t)CHUNK * SMA_CSTEPS * SMA_ROW)
        + (colf2 + tid);

    const float inv_q = 1.0f / 12.0f;
    const float k1312 = 13.0f / 12.0f;

#pragma unroll 1
    for (int blk = 0; blk < SMA_CSTEPS / SMA_Q; blk++) {
#pragma unroll
        for (int u = 0; u < SMA_Q; u++) {
            float mx = sx * inv_q;
            float my = sy * inv_q;
            d[(size_t)u * SMA_ROW2] = make_float2(mx, my);
            sx = fmaf(sx, k1312, -wx[u]);
            sy = fmaf(sy, k1312, -wy[u]);
            wx[u] = mx;
            wy[u] = my;
        }
        d += (size_t)SMA_Q * SMA_ROW2;
    }
}

template <int CHUNK>
__device__ __forceinline__ void sma_dispatch(
    const float* __restrict__ in, float* __restrict__ out)
{
    if (blockIdx.x < NFULL) sma_block_full<CHUNK>(in, out);
    else                    sma_block_part<CHUNK>(in, out);
}

__global__ __launch_bounds__(128)
void sma_main_kernel(const float* __restrict__ in, float* __restrict__ out) {
    switch (blockIdx.z) {
        case 0: sma_dispatch<0>(in, out); break;
        case 1: sma_dispatch<1>(in, out); break;
        case 2: sma_dispatch<2>(in, out); break;
        case 3: sma_dispatch<3>(in, out); break;
        case 4: sma_dispatch<4>(in, out); break;
        case 5: sma_dispatch<5>(in, out); break;
        case 6: sma_dispatch<6>(in, out); break;
        default: break;
    }
}

extern "C" void kernel_launch(void* const* d_in, const int* in_sizes, int n_in,
                              void* d_out, int out_size) {
    (void)in_sizes; (void)n_in; (void)out_size;
    const float* in = (const float*)d_in[0];
    float* out = (float*)d_out;

    dim3 grid(NFULL + 1, SMA_BATCH, SMA_CHUNKS);  // (11, 64, 7)
    sma_main_kernel<<<grid, 128>>>(in, out);
}

// round 10
// speedup vs baseline: 2.2841x; 1.2801x over previous
#include <cuda_runtime.h>
#include <cuda_bf16.h>
#include <stdint.h>

// SimpleMovingAverage: history (64, 336, 862, 3) f32.
// window = last Q=12 steps; 336 iterations of m = mean(window), push m.
//
// Time split: 7 chunks x 48 steps (48 = 4*12 -> register ring statically
// indexed). Chunk start windows from compile-time matrices A^(48c) in
// __constant__ memory. Per-step critical path: 1 FFMA per component:
//   m = s/12;  s = fma(s, 13/12, -w[u]).
//
// R8 lesson: SMEM staging + barriers kill occupancy; alignment must be fixed
// in-registers. R9: each thread owns 4 consecutive floats (16 B). Output row
// byte-phase is 8*(row&1) and row parity is compile-time in the unrolled
// loop, so even rows emit one aligned STG.128 and odd rows two aligned
// STG.64. -25% store instructions, -17% L1 wavefronts vs float2, no SMEM,
// no barriers.

#define SMA_Q       12
#define SMA_INLEN   336
#define SMA_OUTLEN  336
#define SMA_ROW     2586          // floats per (b,t) row; 10344 B; %4 == 2
#define SMA_BATCH   64

#define SMA_CHUNKS  7
#define SMA_CSTEPS  (SMA_OUTLEN / SMA_CHUNKS)  // 48 = 4 * 12

#define SMA_W4      128                       // float4 lanes per full block
#define FULLB       5                         // 5*128*4 = 2560 floats covered
#define PART_F2     13                        // (2586 - 2560)/2 float2 lanes

struct SmaMats { float m[SMA_CHUNKS - 1][SMA_Q][SMA_Q]; };

static constexpr SmaMats sma_compute_mats() {
    SmaMats r = {};
    for (int k = 0; k < SMA_Q; k++) {
        float w[SMA_Q] = {};
        for (int i = 0; i < SMA_Q; i++) w[i] = (i == k) ? 1.0f : 0.0f;
        float s = 1.0f;
        for (int c = 0; c < SMA_CHUNKS - 1; c++) {
            for (int t = 0; t < SMA_CSTEPS; t++) {
                int u = t % SMA_Q;
                float mean = s * (1.0f / 12.0f);
                s = s * (13.0f / 12.0f) - w[u];
                w[u] = mean;
            }
            for (int j = 0; j < SMA_Q; j++) r.m[c][k][j] = w[j];
        }
    }
    return r;
}

__constant__ SmaMats c_MATS = sma_compute_mats();

// ---------------- full blocks: float4 per thread ----------------

template <int CHUNK>
__device__ __forceinline__ void sma_full(const float* __restrict__ in,
                                         float* __restrict__ out)
{
    const int tid = threadIdx.x;
    const int cb  = blockIdx.x;               // 0..FULLB-1
    const int b   = blockIdx.y;
    const int c0  = cb * (SMA_W4 * 4) + tid * 4;   // float index in row, %4==0

    // Input tail rows: global row (b*336 + 324 + k); parity == k (324 even,
    // b*336 even). Float offset of row r0+k is ...*SMA_ROW + c0; since
    // SMA_ROW%4==2, k even -> 16B aligned, k odd -> 8B aligned.
    const float* __restrict__ srow =
        in + ((size_t)b * SMA_INLEN + (SMA_INLEN - SMA_Q)) * SMA_ROW + c0;

    float4 w[SMA_Q];
    float4 s;

    if (CHUNK == 0) {
        s = make_float4(0.f, 0.f, 0.f, 0.f);
#pragma unroll
        for (int k = 0; k < SMA_Q; k++) {
            const float* p = srow + (size_t)k * SMA_ROW;
            float4 v;
            if ((k & 1) == 0) {
                v = *reinterpret_cast<const float4*>(p);
            } else {
                float2 a = *reinterpret_cast<const float2*>(p);
                float2 c = *reinterpret_cast<const float2*>(p + 2);
                v = make_float4(a.x, a.y, c.x, c.y);
            }
            w[k] = v;
            s.x += v.x; s.y += v.y; s.z += v.z; s.w += v.w;
        }
    } else {
#pragma unroll
        for (int j = 0; j < SMA_Q; j++) w[j] = make_float4(0.f, 0.f, 0.f, 0.f);
#pragma unroll
        for (int k = 0; k < SMA_Q; k++) {
            const float* p = srow + (size_t)k * SMA_ROW;
            float4 v;
            if ((k & 1) == 0) {
                v = *reinterpret_cast<const float4*>(p);
            } else {
                float2 a = *reinterpret_cast<const float2*>(p);
                float2 c = *reinterpret_cast<const float2*>(p + 2);
                v = make_float4(a.x, a.y, c.x, c.y);
            }
#pragma unroll
            for (int j = 0; j < SMA_Q; j++) {
                float cf = c_MATS.m[CHUNK - 1][k][j];
                w[j].x = fmaf(cf, v.x, w[j].x);
                w[j].y = fmaf(cf, v.y, w[j].y);
                w[j].z = fmaf(cf, v.z, w[j].z);
                w[j].w = fmaf(cf, v.w, w[j].w);
            }
        }
        s = make_float4(0.f, 0.f, 0.f, 0.f);
#pragma unroll
        for (int j = 0; j < SMA_Q; j++) {
            s.x += w[j].x; s.y += w[j].y; s.z += w[j].z; s.w += w[j].w;
        }
    }

    const float inv_q = 1.0f / 12.0f;
    const float k1312 = 13.0f / 12.0f;

    // Output rows: rowbase = b*336 + CHUNK*48 (even), + blk*12 (even) + u.
    // Row parity == u&1 (compile-time in the unrolled loop).
    float* __restrict__ drow =
        out + ((size_t)b * SMA_OUTLEN + (size_t)CHUNK * SMA_CSTEPS) * SMA_ROW + c0;

#pragma unroll 1
    for (int blk = 0; blk < SMA_CSTEPS / SMA_Q; blk++) {
#pragma unroll
        for (int u = 0; u < SMA_Q; u++) {
            float4 m;
            m.x = s.x * inv_q; m.y = s.y * inv_q;
            m.z = s.z * inv_q; m.w = s.w * inv_q;

            float* p = drow + (size_t)u * SMA_ROW;
            if ((u & 1) == 0) {
                *reinterpret_cast<float4*>(p) = m;           // 16B aligned
            } else {
                *reinterpret_cast<float2*>(p)     = make_float2(m.x, m.y);
                *reinterpret_cast<float2*>(p + 2) = make_float2(m.z, m.w);
            }

            s.x = fmaf(s.x, k1312, -w[u].x);
            s.y = fmaf(s.y, k1312, -w[u].y);
            s.z = fmaf(s.z, k1312, -w[u].z);
            s.w = fmaf(s.w, k1312, -w[u].w);
            w[u] = m;
        }
        drow += (size_t)SMA_Q * SMA_ROW;
    }
}

// ---------------- partial block: 13 float2 lanes ----------------

template <int CHUNK>
__device__ __forceinline__ void sma_part(const float* __restrict__ in,
                                         float* __restrict__ out)
{
    const int tid = threadIdx.x;
    if (tid >= PART_F2) return;
    const int b  = blockIdx.y;
    const int c0 = FULLB * SMA_W4 * 4 + tid * 2;   // float index, 2560 + 2t

    const float* __restrict__ srow =
        in + ((size_t)b * SMA_INLEN + (SMA_INLEN - SMA_Q)) * SMA_ROW + c0;

    float wx[SMA_Q], wy[SMA_Q];
    float sx = 0.f, sy = 0.f;

    if (CHUNK == 0) {
#pragma unroll
        for (int k = 0; k < SMA_Q; k++) {
            float2 v = *reinterpret_cast<const float2*>(srow + (size_t)k * SMA_ROW);
            wx[k] = v.x; wy[k] = v.y;
            sx += v.x;   sy += v.y;
        }
    } else {
#pragma unroll
        for (int j = 0; j < SMA_Q; j++) { wx[j] = 0.f; wy[j] = 0.f; }
#pragma unroll
        for (int k = 0; k < SMA_Q; k++) {
            float2 v = *reinterpret_cast<const float2*>(srow + (size_t)k * SMA_ROW);
#pragma unroll
            for (int j = 0; j < SMA_Q; j++) {
                float c = c_MATS.m[CHUNK - 1][k][j];
                wx[j] = fmaf(c, v.x, wx[j]);
                wy[j] = fmaf(c, v.y, wy[j]);
            }
        }
#pragma unroll
        for (int j = 0; j < SMA_Q; j++) { sx += wx[j]; sy += wy[j]; }
    }

    const float inv_q = 1.0f / 12.0f;
    const float k1312 = 13.0f / 12.0f;

    float* __restrict__ drow =
        out + ((size_t)b * SMA_OUTLEN + (size_t)CHUNK * SMA_CSTEPS) * SMA_ROW + c0;

#pragma unroll 1
    for (int blk = 0; blk < SMA_CSTEPS / SMA_Q; blk++) {
#pragma unroll
        for (int u = 0; u < SMA_Q; u++) {
            float mx = sx * inv_q;
            float my = sy * inv_q;
            *reinterpret_cast<float2*>(drow + (size_t)u * SMA_ROW)
                = make_float2(mx, my);
            sx = fmaf(sx, k1312, -wx[u]);
            sy = fmaf(sy, k1312, -wy[u]);
            wx[u] = mx;
            wy[u] = my;
        }
        drow += (size_t)SMA_Q * SMA_ROW;
    }
}

template <int CHUNK>
__device__ __forceinline__ void sma_dispatch(const float* __restrict__ in,
                                             float* __restrict__ out)
{
    if (blockIdx.x < FULLB) sma_full<CHUNK>(in, out);
    else                    sma_part<CHUNK>(in, out);
}

__global__ __launch_bounds__(128)
void sma_main_kernel(const float* __restrict__ in, float* __restrict__ out) {
    switch (blockIdx.z) {
        case 0: sma_dispatch<0>(in, out); break;
        case 1: sma_dispatch<1>(in, out); break;
        case 2: sma_dispatch<2>(in, out); break;
        case 3: sma_dispatch<3>(in, out); break;
        case 4: sma_dispatch<4>(in, out); break;
        case 5: sma_dispatch<5>(in, out); break;
        case 6: sma_dispatch<6>(in, out); break;
        default: break;
    }
}

extern "C" void kernel_launch(void* const* d_in, const int* in_sizes, int n_in,
                              void* d_out, int out_size) {
    (void)in_sizes; (void)n_in; (void)out_size;
    const float* in = (const float*)d_in[0];
    float* out = (float*)d_out;

    dim3 grid(FULLB + 1, SMA_BATCH, SMA_CHUNKS);  // (6, 64, 7)
    sma_main_kernel<<<grid, 128>>>(in, out);
}

// round 11
// speedup vs baseline: 2.2964x; 1.0054x over previous
#include <cuda_runtime.h>
#include <cuda_bf16.h>
#include <stdint.h>

// SimpleMovingAverage: history (64, 336, 862, 3) f32.
// window = last Q=12 steps; 336 iterations of m = mean(window), push m.
//
// Recurrence is linear -> time split into 14 chunks x 24 steps (24 = 2*12
// keeps the register ring statically indexed). Chunk c rebuilds its start
// window from the 12 input rows via A^(24c), with coefficients computed at
// compile time into __constant__ memory and read as float4 (constant port,
// zero L1tex traffic). Chunk index is DYNAMIC (one code path; 14 template
// clones would thrash I$).
//
// Store path (R9, best so far): each thread owns 4 consecutive floats.
// Output row byte-phase is 8*(row&1); row parity is compile-time inside the
// 12-step unroll, so even rows emit one aligned STG.128 and odd rows two
// aligned STG.64. Per-step critical path: 1 FFMA per component:
//   m = s/12;  s = fma(s, 13/12, -w[u]).
//
// R10 change vs R9: 7->14 chunks. 2688 -> 5376 blocks = ~9 waves, shrinking
// the wave-tail from ~0.5 wave to ~0.1 (R9's achieved occ 25.9% vs 37.5%
// theoretical was tail quantization).

#define SMA_Q       12
#define SMA_INLEN   336
#define SMA_OUTLEN  336
#define SMA_ROW     2586          // floats per (b,t) row; 10344 B; %4 == 2
#define SMA_BATCH   64

#define SMA_CHUNKS  14
#define SMA_CSTEPS  (SMA_OUTLEN / SMA_CHUNKS)  // 24 = 2 * 12

#define SMA_W4      128                       // float4 lanes per full block
#define FULLB       5                         // 5*128*4 = 2560 floats covered
#define PART_F2     13                        // (2586 - 2560)/2 float2 lanes

struct SmaMats { float m[SMA_CHUNKS - 1][SMA_Q][SMA_Q]; };

static constexpr SmaMats sma_compute_mats() {
    SmaMats r = {};
    for (int k = 0; k < SMA_Q; k++) {
        float w[SMA_Q] = {};
        for (int i = 0; i < SMA_Q; i++) w[i] = (i == k) ? 1.0f : 0.0f;
        float s = 1.0f;
        for (int c = 0; c < SMA_CHUNKS - 1; c++) {
            for (int t = 0; t < SMA_CSTEPS; t++) {
                int u = t % SMA_Q;
                float mean = s * (1.0f / 12.0f);
                s = s * (13.0f / 12.0f) - w[u];
                w[u] = mean;
            }
            for (int j = 0; j < SMA_Q; j++) r.m[c][k][j] = w[j];
        }
    }
    return r;
}

__constant__ SmaMats c_MATS = sma_compute_mats();

// ---------------- full blocks: float4 per thread ----------------

__device__ __forceinline__ void sma_full(const float* __restrict__ in,
                                         float* __restrict__ out,
                                         int chunk)
{
    const int tid = threadIdx.x;
    const int cb  = blockIdx.x;               // 0..FULLB-1
    const int b   = blockIdx.y;
    const int c0  = cb * (SMA_W4 * 4) + tid * 4;   // float index in row, %4==0

    // Input tail rows: row (b*336 + 324 + k), parity == k. SMA_ROW%4==2, so
    // k even -> 16B aligned (LDG.128), k odd -> 8B aligned (2x LDG.64).
    const float* __restrict__ srow =
        in + ((size_t)b * SMA_INLEN + (SMA_INLEN - SMA_Q)) * SMA_ROW + c0;

    float4 w[SMA_Q];
    float4 s = make_float4(0.f, 0.f, 0.f, 0.f);

    if (chunk == 0) {
#pragma unroll
        for (int k = 0; k < SMA_Q; k++) {
            const float* p = srow + (size_t)k * SMA_ROW;
            float4 v;
            if ((k & 1) == 0) {
                v = *reinterpret_cast<const float4*>(p);
            } else {
                float2 a = *reinterpret_cast<const float2*>(p);
                float2 c = *reinterpret_cast<const float2*>(p + 2);
                v = make_float4(a.x, a.y, c.x, c.y);
            }
            w[k] = v;
            s.x += v.x; s.y += v.y; s.z += v.z; s.w += v.w;
        }
    } else {
        const float4* __restrict__ M4 =
            reinterpret_cast<const float4*>(&c_MATS.m[chunk - 1][0][0]);
#pragma unroll
        for (int j = 0; j < SMA_Q; j++) w[j] = make_float4(0.f, 0.f, 0.f, 0.f);
#pragma unroll
        for (int k = 0; k < SMA_Q; k++) {
            const float* p = srow + (size_t)k * SMA_ROW;
            float4 v;
            if ((k & 1) == 0) {
                v = *reinterpret_cast<const float4*>(p);
            } else {
                float2 a = *reinterpret_cast<const float2*>(p);
                float2 c = *reinterpret_cast<const float2*>(p + 2);
                v = make_float4(a.x, a.y, c.x, c.y);
            }
            // 12 coefficients for this k as 3 float4 constant loads
#pragma unroll
            for (int j4 = 0; j4 < 3; j4++) {
                float4 cc = M4[k * 3 + j4];
                float cf;
                cf = cc.x;
                w[j4*4+0].x = fmaf(cf, v.x, w[j4*4+0].x);
                w[j4*4+0].y = fmaf(cf, v.y, w[j4*4+0].y);
                w[j4*4+0].z = fmaf(cf, v.z, w[j4*4+0].z);
                w[j4*4+0].w = fmaf(cf, v.w, w[j4*4+0].w);
                cf = cc.y;
                w[j4*4+1].x = fmaf(cf, v.x, w[j4*4+1].x);
                w[j4*4+1].y = fmaf(cf, v.y, w[j4*4+1].y);
                w[j4*4+1].z = fmaf(cf, v.z, w[j4*4+1].z);
                w[j4*4+1].w = fmaf(cf, v.w, w[j4*4+1].w);
                cf = cc.z;
                w[j4*4+2].x = fmaf(cf, v.x, w[j4*4+2].x);
                w[j4*4+2].y = fmaf(cf, v.y, w[j4*4+2].y);
                w[j4*4+2].z = fmaf(cf, v.z, w[j4*4+2].z);
                w[j4*4+2].w = fmaf(cf, v.w, w[j4*4+2].w);
                cf = cc.w;
                w[j4*4+3].x = fmaf(cf, v.x, w[j4*4+3].x);
                w[j4*4+3].y = fmaf(cf, v.y, w[j4*4+3].y);
                w[j4*4+3].z = fmaf(cf, v.z, w[j4*4+3].z);
                w[j4*4+3].w = fmaf(cf, v.w, w[j4*4+3].w);
            }
        }
#pragma unroll
        for (int j = 0; j < SMA_Q; j++) {
            s.x += w[j].x; s.y += w[j].y; s.z += w[j].z; s.w += w[j].w;
        }
    }

    const float inv_q = 1.0f / 12.0f;
    const float k1312 = 13.0f / 12.0f;

    // Output rows: rowbase = b*336 + chunk*24 (even) + blk*12 (even) + u,
    // so row parity == u&1 (compile-time in the unrolled loop).
    float* __restrict__ drow =
        out + ((size_t)b * SMA_OUTLEN + (size_t)chunk * SMA_CSTEPS) * SMA_ROW + c0;

#pragma unroll 1
    for (int blk = 0; blk < SMA_CSTEPS / SMA_Q; blk++) {
#pragma unroll
        for (int u = 0; u < SMA_Q; u++) {
            float4 m;
            m.x = s.x * inv_q; m.y = s.y * inv_q;
            m.z = s.z * inv_q; m.w = s.w * inv_q;

            float* p = drow + (size_t)u * SMA_ROW;
            if ((u & 1) == 0) {
                *reinterpret_cast<float4*>(p) = m;           // 16B aligned
            } else {
                *reinterpret_cast<float2*>(p)     = make_float2(m.x, m.y);
                *reinterpret_cast<float2*>(p + 2) = make_float2(m.z, m.w);
            }

            s.x = fmaf(s.x, k1312, -w[u].x);
            s.y = fmaf(s.y, k1312, -w[u].y);
            s.z = fmaf(s.z, k1312, -w[u].z);
            s.w = fmaf(s.w, k1312, -w[u].w);
            w[u] = m;
        }
        drow += (size_t)SMA_Q * SMA_ROW;
    }
}

// ---------------- partial block: 13 float2 lanes ----------------

__device__ __forceinline__ void sma_part(const float* __restrict__ in,
                                         float* __restrict__ out,
                                         int chunk)
{
    const int tid = threadIdx.x;
    if (tid >= PART_F2) return;
    const int b  = blockIdx.y;
    const int c0 = FULLB * SMA_W4 * 4 + tid * 2;   // float index, 2560 + 2t

    const float* __restrict__ srow =
        in + ((size_t)b * SMA_INLEN + (SMA_INLEN - SMA_Q)) * SMA_ROW + c0;

    float wx[SMA_Q], wy[SMA_Q];
    float sx = 0.f, sy = 0.f;

    if (chunk == 0) {
#pragma unroll
        for (int k = 0; k < SMA_Q; k++) {
            float2 v = *reinterpret_cast<const float2*>(srow + (size_t)k * SMA_ROW);
            wx[k] = v.x; wy[k] = v.y;
            sx += v.x;   sy += v.y;
        }
    } else {
#pragma unroll
        for (int j = 0; j < SMA_Q; j++) { wx[j] = 0.f; wy[j] = 0.f; }
#pragma unroll
        for (int k = 0; k < SMA_Q; k++) {
            float2 v = *reinterpret_cast<const float2*>(srow + (size_t)k * SMA_ROW);
#pragma unroll
            for (int j = 0; j < SMA_Q; j++) {
                float c = c_MATS.m[chunk - 1][k][j];
                wx[j] = fmaf(c, v.x, wx[j]);
                wy[j] = fmaf(c, v.y, wy[j]);
            }
        }
#pragma unroll
        for (int j = 0; j < SMA_Q; j++) { sx += wx[j]; sy += wy[j]; }
    }

    const float inv_q = 1.0f / 12.0f;
    const float k1312 = 13.0f / 12.0f;

    float* __restrict__ drow =
        out + ((size_t)b * SMA_OUTLEN + (size_t)chunk * SMA_CSTEPS) * SMA_ROW + c0;

#pragma unroll 1
    for (int blk = 0; blk < SMA_CSTEPS / SMA_Q; blk++) {
#pragma unroll
        for (int u = 0; u < SMA_Q; u++) {
            float mx = sx * inv_q;
            float my = sy * inv_q;
            *reinterpret_cast<float2*>(drow + (size_t)u * SMA_ROW)
                = make_float2(mx, my);
            sx = fmaf(sx, k1312, -wx[u]);
            sy = fmaf(sy, k1312, -wy[u]);
            wx[u] = mx;
            wy[u] = my;
        }
        drow += (size_t)SMA_Q * SMA_ROW;
    }
}

__global__ __launch_bounds__(128)
void sma_main_kernel(const float* __restrict__ in, float* __restrict__ out) {
    const int chunk = blockIdx.z;
    if (blockIdx.x < FULLB) sma_full(in, out, chunk);
    else                    sma_part(in, out, chunk);
}

extern "C" void kernel_launch(void* const* d_in, const int* in_sizes, int n_in,
                              void* d_out, int out_size) {
    (void)in_sizes; (void)n_in; (void)out_size;
    const float* in = (const float*)d_in[0];
    float* out = (float*)d_out;

    dim3 grid(FULLB + 1, SMA_BATCH, SMA_CHUNKS);  // (6, 64, 14) = 5376 blocks
    sma_main_kernel<<<grid, 128>>>(in, out);
}